// round 13
// baseline (speedup 1.0000x reference)
#include <cuda_runtime.h>

#define E_TOT   40000
#define N_NODES 4000
#define NCOEF   25
#define HID     64
#define FIN     128
#define F3      640

// ---------------- scratch (device globals; no allocs allowed) ----------------
__device__ __align__(16) float g_m0[(long long)E_TOT * F3]; // 102.4 MB
__device__ int   g_cnt[N_NODES];
__device__ int   g_off[N_NODES + 1];
__device__ int   g_list[E_TOT];

typedef unsigned long long ull;

// ---------------- small helpers ----------------
__device__ __forceinline__ ull pack2(float x) {
    ull r;
    asm("mov.b64 %0, {%1, %1};" : "=l"(r) : "f"(x));
    return r;
}
__device__ __forceinline__ ull pack_pair(float lo, float hi) {
    ull r;
    asm("mov.b64 %0, {%1, %2};" : "=l"(r) : "f"(lo), "f"(hi));
    return r;
}
__device__ __forceinline__ void unpack2(ull v, float& lo, float& hi) {
    asm("mov.b64 {%0, %1}, %2;" : "=f"(lo), "=f"(hi) : "l"(v));
}
__device__ __forceinline__ void fma2(ull& c, ull a, ull b) {
    asm("fma.rn.f32x2 %0, %1, %2, %0;" : "+l"(c) : "l"(a), "l"(b));
}
__device__ __forceinline__ float allred16(float v) {
    v += __shfl_xor_sync(0xffffffffu, v, 8, 16);
    v += __shfl_xor_sync(0xffffffffu, v, 4, 16);
    v += __shfl_xor_sync(0xffffffffu, v, 2, 16);
    v += __shfl_xor_sync(0xffffffffu, v, 1, 16);
    return v;
}

#define CP_ASYNC16(dst, src) \
    asm volatile("cp.async.cg.shared.global [%0], [%1], 16;" :: "r"(dst), "l"(src))
#define CP_ASYNC4(dst, src) \
    asm volatile("cp.async.ca.shared.global [%0], [%1], 4;" :: "r"(dst), "l"(src))
#define CP_COMMIT() asm volatile("cp.async.commit_group;")
#define CP_WAIT(n)  asm volatile("cp.async.wait_group %0;" :: "n"(n))

// ---------------- edge-list building ----------------
__global__ void k_zero() {
    int i = blockIdx.x * blockDim.x + threadIdx.x;
    if (i < N_NODES) g_cnt[i] = 0;
}

__global__ void k_count(const int* __restrict__ ei, const int* __restrict__ noff) {
    int e = blockIdx.x * blockDim.x + threadIdx.x;
    if (e < E_TOT) {
        int d = ei[E_TOT + e] - noff[0];
        atomicAdd(&g_cnt[d], 1);
    }
}

// single-CTA: exclusive scan of counts -> g_off, then fill g_list via smem cursors
__global__ void __launch_bounds__(1024) k_scanfill(
    const int* __restrict__ ei, const int* __restrict__ noff) {
    __shared__ int s[1024];
    __shared__ int s_cur[N_NODES];
    const int tid = threadIdx.x;
    int v[4];
    int tot = 0;
#pragma unroll
    for (int j = 0; j < 4; j++) {
        int idx = tid * 4 + j;
        v[j] = (idx < N_NODES) ? g_cnt[idx] : 0;
        tot += v[j];
    }
    s[tid] = tot;
    __syncthreads();
    for (int off = 1; off < 1024; off <<= 1) {
        int t = (tid >= off) ? s[tid - off] : 0;
        __syncthreads();
        s[tid] += t;
        __syncthreads();
    }
    int run = s[tid] - tot;  // exclusive
#pragma unroll
    for (int j = 0; j < 4; j++) {
        int idx = tid * 4 + j;
        if (idx < N_NODES) {
            g_off[idx] = run;
            s_cur[idx] = run;
        }
        run += v[j];
    }
    if (tid == 1023) g_off[N_NODES] = s[1023];
    __syncthreads();
    const int nf = noff[0];
    for (int e = tid; e < E_TOT; e += 1024) {
        int d = ei[E_TOT + e] - nf;
        int pos = atomicAdd(&s_cur[d], 1);
        g_list[pos] = e;
    }
}

// ---------------- fused MLP: (Lin->LN->SiLU)x2 then Lin3 + env ----------------
// CTA: 64 edges, 256 threads, target 4 CTAs/SM.
// Phase A map: eg4 = tid>>4 (4 edges), fg4 = tid&15 (4 feats)
// Phase B map: egr = tid>>4 (4 edges), fg = tid&15 (8 feats)
// s_ht2 holds h2 DUPLICATED per element: [k][2e] == [k][2e+1]  -> LDS64 = free splat
__global__ void __launch_bounds__(256, 4) k_mlp(
    const float* __restrict__ x_edge, const float* __restrict__ edge_distance,
    const float* __restrict__ w1, const float* __restrict__ b1,
    const float* __restrict__ g1, const float* __restrict__ be1,
    const float* __restrict__ w2, const float* __restrict__ b2,
    const float* __restrict__ g2, const float* __restrict__ be2,
    const float* __restrict__ w3, const float* __restrict__ b3) {
    // layout (floats):
    //   [0, 8448)     : phase A: s_xe stride 132 / s_h stride 68
    //                   phase B: s_ht2 [64 k][130] (duplicated h2; 8320 used)
    //   [8448, 10496) : s_w3: 2 buffers of 8k x 128f
    __shared__ __align__(16) float sbuf[10496];  // 41984 B
    __shared__ __align__(16) float s_env[64];
    float* s_xe  = sbuf;
    float* s_h   = sbuf;
    float* s_ht2 = sbuf;
    float* s_w3  = sbuf + 8448;

    const int tid = threadIdx.x;
    const int e0 = blockIdx.x * 64;

    {   // load x_edge tile [64][128] -> padded smem
        const float4* src = reinterpret_cast<const float4*>(x_edge + (long long)e0 * FIN);
#pragma unroll
        for (int i = tid; i < 64 * 32; i += 256) {
            int e = i >> 5, k4 = i & 31;
            float4 v = src[i];
            *reinterpret_cast<float4*>(&s_xe[e * 132 + k4 * 4]) = v;
        }
    }
    if (tid < 64) {
        float d = edge_distance[e0 + tid] * (1.0f / 12.0f);
        float env = 0.f;
        if (d < 1.f) {
            float d2 = d * d, d4 = d2 * d2, d5 = d4 * d;
            env = 1.f + d5 * (-21.f + d * 35.f - d2 * 15.f);
        }
        s_env[tid] = env * 0.2f;  // env / RESCALE
    }
    __syncthreads();

    const int fg4 = tid & 15;
    const int eg4 = tid >> 4;

    // -------- layer 1 --------
    ull acc1[4][2] = {};
    for (int k = 0; k < 128; k++) {
        float4 b = __ldg(reinterpret_cast<const float4*>(w1 + k * 64 + fg4 * 4));
        ull b0 = pack_pair(b.x, b.y), bq = pack_pair(b.z, b.w);
#pragma unroll
        for (int r = 0; r < 4; r++) {
            ull a2 = pack2(s_xe[(eg4 * 4 + r) * 132 + k]);
            fma2(acc1[r][0], a2, b0);
            fma2(acc1[r][1], a2, bq);
        }
    }
    float h1v[4][4];
    {
        float4 bb = __ldg(reinterpret_cast<const float4*>(b1 + fg4 * 4));
        float4 gg = __ldg(reinterpret_cast<const float4*>(g1 + fg4 * 4));
        float4 ee = __ldg(reinterpret_cast<const float4*>(be1 + fg4 * 4));
        float ba[4] = {bb.x, bb.y, bb.z, bb.w};
        float ga[4] = {gg.x, gg.y, gg.z, gg.w};
        float ea[4] = {ee.x, ee.y, ee.z, ee.w};
#pragma unroll
        for (int r = 0; r < 4; r++) {
            float hv[4], s1 = 0.f;
            unpack2(acc1[r][0], hv[0], hv[1]);
            unpack2(acc1[r][1], hv[2], hv[3]);
#pragma unroll
            for (int j = 0; j < 4; j++) { hv[j] += ba[j]; s1 += hv[j]; }
            s1 = allred16(s1);
            float mu = s1 * (1.f / 64.f);
            float s2 = 0.f;
#pragma unroll
            for (int j = 0; j < 4; j++) { float d = hv[j] - mu; s2 += d * d; }
            s2 = allred16(s2);
            float rstd = rsqrtf(s2 * (1.f / 64.f) + 1e-5f);
#pragma unroll
            for (int j = 0; j < 4; j++) {
                float y = (hv[j] - mu) * rstd * ga[j] + ea[j];
                h1v[r][j] = y / (1.f + __expf(-y));  // SiLU
            }
        }
    }
    __syncthreads();  // s_xe reads done
#pragma unroll
    for (int r = 0; r < 4; r++)
#pragma unroll
        for (int j = 0; j < 4; j++) s_h[(eg4 * 4 + r) * 68 + fg4 * 4 + j] = h1v[r][j];
    __syncthreads();

    // -------- layer 2 --------
    ull acc2[4][2] = {};
    for (int k = 0; k < 64; k++) {
        float4 b = __ldg(reinterpret_cast<const float4*>(w2 + k * 64 + fg4 * 4));
        ull b0 = pack_pair(b.x, b.y), bq = pack_pair(b.z, b.w);
#pragma unroll
        for (int r = 0; r < 4; r++) {
            ull a2 = pack2(s_h[(eg4 * 4 + r) * 68 + k]);
            fma2(acc2[r][0], a2, b0);
            fma2(acc2[r][1], a2, bq);
        }
    }
    __syncthreads();  // all h1 reads done before s_ht2 overwrites the region

    const int kr = tid >> 5;      // 0..7  (w3 staging row)
    const int cw = tid & 31;      // x4 floats = 128 cols

    // stage w3 chunks 0 and 1 (fc=0, kc=0/1) while LN2 runs
    {
        const float* src0 = w3 + (long long)kr * 640 + cw * 4;
        unsigned int d0 = (unsigned int)__cvta_generic_to_shared(&s_w3[kr * 128 + cw * 4]);
        CP_ASYNC16(d0, src0);
        CP_COMMIT();
        const float* src1 = w3 + (long long)(8 + kr) * 640 + cw * 4;
        unsigned int d1 = (unsigned int)__cvta_generic_to_shared(&s_w3[1024 + kr * 128 + cw * 4]);
        CP_ASYNC16(d1, src1);
        CP_COMMIT();
    }

    {   // LN2 + SiLU, store h2 DUPLICATED into s_ht2[k][2e],[k][2e+1]
        float4 bb = __ldg(reinterpret_cast<const float4*>(b2 + fg4 * 4));
        float4 gg = __ldg(reinterpret_cast<const float4*>(g2 + fg4 * 4));
        float4 ee = __ldg(reinterpret_cast<const float4*>(be2 + fg4 * 4));
        float ba[4] = {bb.x, bb.y, bb.z, bb.w};
        float ga[4] = {gg.x, gg.y, gg.z, gg.w};
        float ea[4] = {ee.x, ee.y, ee.z, ee.w};
#pragma unroll
        for (int r = 0; r < 4; r++) {
            float hv[4], s1 = 0.f;
            unpack2(acc2[r][0], hv[0], hv[1]);
            unpack2(acc2[r][1], hv[2], hv[3]);
#pragma unroll
            for (int j = 0; j < 4; j++) { hv[j] += ba[j]; s1 += hv[j]; }
            s1 = allred16(s1);
            float mu = s1 * (1.f / 64.f);
            float s2 = 0.f;
#pragma unroll
            for (int j = 0; j < 4; j++) { float d = hv[j] - mu; s2 += d * d; }
            s2 = allred16(s2);
            float rstd = rsqrtf(s2 * (1.f / 64.f) + 1e-5f);
#pragma unroll
            for (int j = 0; j < 4; j++) {
                float y = (hv[j] - mu) * rstd * ga[j] + ea[j];
                float sv = y / (1.f + __expf(-y));
                // duplicated store: k = fg4*4+j, e = eg4*4+r
                *reinterpret_cast<ull*>(
                    &s_ht2[(fg4 * 4 + j) * 130 + 2 * (eg4 * 4 + r)]) = pack2(sv);
            }
        }
    }
    __syncthreads();

    // -------- layer 3: 40 chunks (fc 0..4 x kc 0..7), 2-buffer cp.async pipe ----
    // thread owns 4 edges (egr*4+e) x 8 feats (fg*8..fg*8+7); acc[e][j] = feat pair
    const int fg  = tid & 15;
    const int egr = tid >> 4;
    const ull* b3u = reinterpret_cast<const ull*>(b3);

    ull acc[4][4];
#pragma unroll 1
    for (int ci = 0; ci < 40; ci++) {
        const int fc = ci >> 3, kc = ci & 7, buf = ci & 1;
        if (kc == 0) {
#pragma unroll
            for (int j = 0; j < 4; j++) {
                ull bv = __ldg(b3u + (fc * 128 + fg * 8) / 2 + j);
                acc[0][j] = bv; acc[1][j] = bv; acc[2][j] = bv; acc[3][j] = bv;
            }
        }
        CP_WAIT(1);
        __syncthreads();
        const float* wb = s_w3 + buf * 1024;
#pragma unroll
        for (int k = 0; k < 8; k++) {
            ull w2v[4], h2v[4];
#pragma unroll
            for (int j = 0; j < 4; j++)
                w2v[j] = *reinterpret_cast<const ull*>(&wb[k * 128 + fg * 8 + 2 * j]);
#pragma unroll
            for (int e = 0; e < 4; e++)
                h2v[e] = *reinterpret_cast<const ull*>(
                    &s_ht2[(kc * 8 + k) * 130 + 2 * (egr * 4 + e)]);
#pragma unroll
            for (int e = 0; e < 4; e++) {
                fma2(acc[e][0], h2v[e], w2v[0]);
                fma2(acc[e][1], h2v[e], w2v[1]);
                fma2(acc[e][2], h2v[e], w2v[2]);
                fma2(acc[e][3], h2v[e], w2v[3]);
            }
        }
        __syncthreads();
        if (ci + 2 < 40) {
            int ci2 = ci + 2;
            const float* src = w3 + (long long)((ci2 & 7) * 8 + kr) * 640
                               + (ci2 >> 3) * 128 + cw * 4;
            unsigned int dst = (unsigned int)__cvta_generic_to_shared(
                &s_w3[buf * 1024 + kr * 128 + cw * 4]);
            CP_ASYNC16(dst, src);
        }
        CP_COMMIT();
        if (kc == 7) {
#pragma unroll
            for (int e = 0; e < 4; e++) {
                int edge = egr * 4 + e;
                float sc = s_env[edge];
                float4 v0, v1;
                float lo, hi;
                unpack2(acc[e][0], lo, hi); v0.x = lo * sc; v0.y = hi * sc;
                unpack2(acc[e][1], lo, hi); v0.z = lo * sc; v0.w = hi * sc;
                unpack2(acc[e][2], lo, hi); v1.x = lo * sc; v1.y = hi * sc;
                unpack2(acc[e][3], lo, hi); v1.z = lo * sc; v1.w = hi * sc;
                long long base = (long long)(e0 + edge) * 640 + fc * 128 + fg * 8;
                *reinterpret_cast<float4*>(&g_m0[base]) = v0;
                *reinterpret_cast<float4*>(&g_m0[base + 4]) = v1;
            }
        }
    }
}

// ---------------- K3: per-node gather, depth-2 cp.async, 3 buffers ----------------
// out[n,i,c] = x[n,i,c] + sum_{e in edges(n)} sum_k wig[e,i,k(k+1)] * m0[e,k,c]
// CTA per node, 160 threads: iq = tid>>5 (5 rows), cq = tid&31 (4 cols)
__global__ void __launch_bounds__(160) k_gather(
    const float* __restrict__ x, const float* __restrict__ wig,
    float* __restrict__ out) {
    __shared__ __align__(16) float s_m0[3][640];  // [k][c]
    __shared__ __align__(16) float s_w[3][128];   // [k*25+i] (125 used)
    const int n = blockIdx.x;
    const int tid = threadIdx.x;
    const int iq = tid >> 5;
    const int cq = tid & 31;
    const int wk = tid / 25;
    const int wi = tid - wk * 25;
    const bool wact = tid < 125;
    const long long wig_off = (long long)wi * 25 + wk * (wk + 1);

    unsigned int sm0[3], sw[3];
#pragma unroll
    for (int b = 0; b < 3; b++) {
        sm0[b] = (unsigned int)__cvta_generic_to_shared(&s_m0[b][tid * 4]);
        sw[b]  = (unsigned int)__cvta_generic_to_shared(&s_w[b][tid]);
    }

    const int beg = g_off[n], end = g_off[n + 1];

    // init accumulators from x (folds the final add, overlaps the loads)
    ull acc[5][2];
#pragma unroll
    for (int r = 0; r < 5; r++) {
        long long off = ((long long)n * 25 + iq * 5 + r) * 128 + cq * 4;
        float4 xv = *reinterpret_cast<const float4*>(&x[off]);
        acc[r][0] = pack_pair(xv.x, xv.y);
        acc[r][1] = pack_pair(xv.z, xv.w);
    }

    // prologue: stage edges beg, beg+1 (commit always to keep group count aligned)
#pragma unroll
    for (int j = 0; j < 2; j++) {
        if (beg + j < end) {
            int e = g_list[beg + j];
            CP_ASYNC16(sm0[j], &g_m0[(long long)e * 640 + tid * 4]);
            if (wact) CP_ASYNC4(sw[j], &wig[(long long)e * 625 + wig_off]);
        }
        CP_COMMIT();
    }

    for (int t = beg; t < end; t++) {
        const int it = t - beg;
        const int buf = it % 3;
        CP_WAIT(1);          // group for edge t complete (for this thread)
        __syncthreads();     // visible to all; all done reading buf (it-1)%3
        if (t + 2 < end) {
            int e = g_list[t + 2];
            int b2 = (it + 2) % 3;
            CP_ASYNC16(sm0[b2], &g_m0[(long long)e * 640 + tid * 4]);
            if (wact) CP_ASYNC4(sw[b2], &wig[(long long)e * 625 + wig_off]);
        }
        CP_COMMIT();
#pragma unroll
        for (int k = 0; k < 5; k++) {
            ull b0 = *reinterpret_cast<const ull*>(&s_m0[buf][k * 128 + cq * 4]);
            ull b1 = *reinterpret_cast<const ull*>(&s_m0[buf][k * 128 + cq * 4 + 2]);
#pragma unroll
            for (int r = 0; r < 5; r++) {
                ull a2 = pack2(s_w[buf][k * 25 + iq * 5 + r]);
                fma2(acc[r][0], a2, b0);
                fma2(acc[r][1], a2, b1);
            }
        }
    }
#pragma unroll
    for (int r = 0; r < 5; r++) {
        long long off = ((long long)n * 25 + iq * 5 + r) * 128 + cq * 4;
        float4 o;
        float lo, hi;
        unpack2(acc[r][0], lo, hi); o.x = lo; o.y = hi;
        unpack2(acc[r][1], lo, hi); o.z = lo; o.w = hi;
        *reinterpret_cast<float4*>(&out[off]) = o;
    }
}

// ---------------- launch ----------------
extern "C" void kernel_launch(void* const* d_in, const int* in_sizes, int n_in,
                              void* d_out, int out_size) {
    const float* x   = (const float*)d_in[0];
    const float* xe  = (const float*)d_in[1];
    const float* ed  = (const float*)d_in[2];
    const float* wig = (const float*)d_in[3];
    const int*   ei  = (const int*)d_in[4];
    const float* w1  = (const float*)d_in[5];
    const float* b1  = (const float*)d_in[6];
    const float* g1  = (const float*)d_in[7];
    const float* be1 = (const float*)d_in[8];
    const float* w2  = (const float*)d_in[9];
    const float* b2  = (const float*)d_in[10];
    const float* g2  = (const float*)d_in[11];
    const float* be2 = (const float*)d_in[12];
    const float* w3  = (const float*)d_in[13];
    const float* b3  = (const float*)d_in[14];
    const int* noff  = (const int*)d_in[15];
    float* out = (float*)d_out;

    k_zero<<<(N_NODES + 255) / 256, 256>>>();
    k_count<<<(E_TOT + 255) / 256, 256>>>(ei, noff);
    k_scanfill<<<1, 1024>>>(ei, noff);
    k_mlp<<<E_TOT / 64, 256>>>(xe, ed, w1, b1, g1, be1, w2, b2, g2, be2, w3, b3);
    k_gather<<<N_NODES, 160>>>(x, wig, out);
    (void)in_sizes; (void)n_in; (void)out_size;
}